// round 11
// baseline (speedup 1.0000x reference)
#include <cuda_runtime.h>
#include <cstdint>

#define DIM_ 64
#define C2_  256
#define HF_  128
#define HW_  256
#define NPIX (HW_*HW_)
#define B_   4
#define NPATCH 1024   // 32x32 patches of 8x8

// scratch (device globals — allocation-free per harness rules)
__device__ float d_h[(size_t)B_*NPATCH*C2_*64];   // patch-major [b][pat][c2][64]
__device__ float d_g[(size_t)B_*NPATCH*HF_*64];   // patch-major [b][pat][c][64]
__device__ float d_Wt[DIM_*C2_];                  // w_in transposed [i][c]
__device__ float d_Wot[HF_*DIM_];                 // w_out transposed [c][o]

using ull = unsigned long long;
__device__ ull d_Kt2[64*C2_];                     // splat-packed kernels [uv][c]

__device__ __forceinline__ void ffma2(ull &d, ull a, ull b){
    asm("fma.rn.f32x2 %0, %1, %2, %0;" : "+l"(d) : "l"(a), "l"(b));
}
__device__ __forceinline__ ull pack2(float lo, float hi){
    ull r; asm("mov.b64 %0, {%1,%2};" : "=l"(r) : "f"(lo), "f"(hi)); return r;
}
__device__ __forceinline__ float2 unpack2(ull p){
    float2 r; asm("mov.b64 {%0,%1}, %2;" : "=f"(r.x), "=f"(r.y) : "l"(p)); return r;
}

// ---------------------------------------------------------------------------
// Kernel 0: spatial kernels K = irfft2(filt) (closed-form cosine sum),
// splat-packed [uv][c]; transpose w_in and w_out.
// ---------------------------------------------------------------------------
__global__ void k_prep(const float* __restrict__ filt, const float* __restrict__ win,
                       const float* __restrict__ wout){
    int t  = blockIdx.x*256 + threadIdx.x;   // 0..16383
    int c  = t & 255;
    int uv = t >> 8;                         // 0..63
    int u  = uv >> 3, v = uv & 7;
    float s = 0.f;
    #pragma unroll
    for (int ky = 0; ky < 8; ky++){
        #pragma unroll
        for (int kx = 0; kx < 5; kx++){
            float w = (kx==0 || kx==4) ? 1.f : 2.f;
            int m = (ky*u + kx*v) & 7;
            s += w * filt[c*40 + ky*5 + kx] * cospif(0.25f * (float)m);
        }
    }
    float sv = s * (1.f/64.f);
    d_Kt2[uv*256 + c] = pack2(sv, sv);
    d_Wt[uv*256 + c] = win[c*64 + uv];       // uv doubles as input-channel index
    if (t < HF_*DIM_){
        int cc = t >> 6, o = t & 63;
        d_Wot[cc*64 + o] = wout[o*128 + cc];
    }
}

// ---------------------------------------------------------------------------
// Kernel 1: fused conv_in (1x1) + per-patch circular conv (= FFT gating).
// 512 threads per (batch,patch): thread = (c2, half). Phase 1 computes 16
// pixel-pairs for its channel, parks in smem hs2[pair][c2] (conflict-free
// 8B-stride columns). Phase 2: thread computes 2 output g-groups (g static
// via template). 16 warps/SM, ~80 regs, no spills.
// ---------------------------------------------------------------------------
template<int G>
__device__ __forceinline__ void do_g(const ull* hs2, int c2, float* ob){
    ull accA[8], accB[8];
    #pragma unroll
    for (int j = 0; j < 8; j++){ accA[j]=0ull; accB[j]=0ull; }
    #pragma unroll
    for (int u = 0; u < 8; u++){
        constexpr int NOP = 0;  (void)NOP;
        int a = (G - u) & 7;
        bool useA = (a < 4);
        int r8 = (a & 3) * 8;
        ull hrow[8];
        #pragma unroll
        for (int col = 0; col < 8; col++) hrow[col] = hs2[(r8+col)*256 + c2];
        #pragma unroll
        for (int v = 0; v < 8; v++){
            ull kvv = __ldg(&d_Kt2[((u<<3)+v)*256 + c2]);
            #pragma unroll
            for (int px = 0; px < 8; px++){
                int col = (px - v) & 7;
                if (useA) ffma2(accA[px], kvv, hrow[col]);
                else      ffma2(accB[px], kvv, hrow[col]);
            }
        }
    }
    float lo[8], hi[8];
    #pragma unroll
    for (int px = 0; px < 8; px++){
        float2 A  = unpack2(accA[px]);
        float2 Bv = unpack2(accB[px]);
        lo[px] = A.x + Bv.y;     // out row G
        hi[px] = A.y + Bv.x;     // out row G+4
    }
    *(float4*)(ob + G*8)       = make_float4(lo[0],lo[1],lo[2],lo[3]);
    *(float4*)(ob + G*8 + 4)   = make_float4(lo[4],lo[5],lo[6],lo[7]);
    *(float4*)(ob + (G+4)*8)   = make_float4(hi[0],hi[1],hi[2],hi[3]);
    *(float4*)(ob + (G+4)*8+4) = make_float4(hi[4],hi[5],hi[6],hi[7]);
}

#define SMEM_MAIN ((64*32 + 32*256) * 8)   // 80 KB

__global__ void __launch_bounds__(512, 1) k_main(const float* __restrict__ x){
    extern __shared__ ull dsm[];
    ull* xs2 = dsm;               // [in_ch][pair]  16KB
    ull* hs2 = dsm + 64*32;       // [pair][c2]     64KB
    int blk = blockIdx.x;
    int b   = blk >> 10;
    int pat = blk & 1023;
    int y0  = (pat >> 5) << 3;
    int x0  = (pat & 31) << 3;
    const float* xb = x + (size_t)b * DIM_ * NPIX;
    int t = threadIdx.x;

    // cooperative load of the 64ch x 8x8 input patch (one slot per thread)
    {
        int i = t >> 3; int pyp = (t >> 1) & 3; int hf = t & 1;
        const float* p0 = xb + (size_t)i*NPIX + (y0+pyp)*HW_ + x0 + hf*4;
        float4 a  = *(const float4*)p0;
        float4 bb = *(const float4*)(p0 + 4*HW_);
        ull* dst = &xs2[i*32 + pyp*8 + hf*4];
        dst[0] = pack2(a.x, bb.x); dst[1] = pack2(a.y, bb.y);
        dst[2] = pack2(a.z, bb.z); dst[3] = pack2(a.w, bb.w);
    }
    __syncthreads();

    int c2   = t & 255;
    int half = t >> 8;

    // phase 1: 16 pixel-pairs for channel c2
    {
        ull acc[16];
        #pragma unroll
        for (int k = 0; k < 16; k++) acc[k] = 0ull;
        #pragma unroll 4
        for (int i = 0; i < 64; i++){
            float wv = __ldg(&d_Wt[(i<<8) + c2]);
            ull wvv = pack2(wv, wv);
            const ulonglong2* xr = (const ulonglong2*)&xs2[i*32 + half*16];
            #pragma unroll
            for (int q = 0; q < 8; q++){
                ulonglong2 xv = xr[q];
                ffma2(acc[2*q],   wvv, xv.x);
                ffma2(acc[2*q+1], wvv, xv.y);
            }
        }
        #pragma unroll
        for (int q = 0; q < 16; q++) hs2[(half*16 + q)*256 + c2] = acc[q];
    }
    __syncthreads();

    // phase 2: two g-groups per thread (g compile-time; half is warp-uniform)
    float* ob = d_h + (((size_t)(b*NPATCH) + pat)*C2_ + c2)*64;
    if (half == 0){
        do_g<0>(hs2, c2, ob);
        do_g<1>(hs2, c2, ob);
    } else {
        do_g<2>(hs2, c2, ob);
        do_g<3>(hs2, c2, ob);
    }
}

// ---------------------------------------------------------------------------
// Kernel 2: depthwise 3x3 (SAME) + exact-gelu gate, patch-major in/out.
// smem tile row stride 265 (odd) -> conflict-free compute loads.
// ---------------------------------------------------------------------------
#define TS_ 265
__device__ __forceinline__ float gelu_exact(float v){
    return 0.5f * v * (1.f + erff(v * 0.70710678118654752f));
}

__global__ void __launch_bounds__(256) k_dw(const float* __restrict__ wdw){
    __shared__ float tA[10*TS_];
    __shared__ float tB[10*TS_];
    int t  = threadIdx.x;
    int sy = blockIdx.x;          // strip (patch row) 0..31
    int c  = blockIdx.y;          // 0..127
    int b  = blockIdx.z;
    int y0 = sy*8;

    if (t < 40){
        int r = t % 10;
        if (t < 10)      tA[r*TS_ + 0]   = 0.f;
        else if (t < 20) tA[r*TS_ + 257] = 0.f;
        else if (t < 30) tB[r*TS_ + 0]   = 0.f;
        else             tB[r*TS_ + 257] = 0.f;
    }

    #pragma unroll
    for (int half = 0; half < 2; half++){
        float* tile = half ? tB : tA;
        int ch = c + half*128;
        const float* src = d_h + ((size_t)(b*NPATCH))*C2_*64 + (size_t)ch*64;
        for (int f = t; f < 640; f += 256){
            int r  = f >> 6;          // 0..9
            int xq = f & 63;          // float4 index across 256 cols
            int y  = y0 - 1 + r;
            float4 v = make_float4(0,0,0,0);
            if (y >= 0 && y < 256){
                int pat = ((y>>3)<<5) + (xq>>1);
                int pix = ((y&7)<<3) + ((xq&1)<<2);
                v = __ldg((const float4*)(src + (size_t)pat*(C2_*64) + pix));
            }
            float* dst = tile + r*TS_ + 1 + xq*4;
            dst[0]=v.x; dst[1]=v.y; dst[2]=v.z; dst[3]=v.w;
        }
    }
    __syncthreads();

    int pat = t >> 3;                 // 0..31 (patch within strip)
    int row = t & 7;                  // 0..7
    int xbase = pat*8;

    float accA[8], accB[8];
    #pragma unroll
    for (int j = 0; j < 8; j++){ accA[j]=0.f; accB[j]=0.f; }

    #pragma unroll
    for (int half = 0; half < 2; half++){
        const float* tile = half ? tB : tA;
        const float* wp = wdw + (c + half*128)*9;
        float w[9];
        #pragma unroll
        for (int k = 0; k < 9; k++) w[k] = __ldg(wp + k);
        float* acc = half ? accB : accA;
        #pragma unroll
        for (int ky = 0; ky < 3; ky++){
            const float* rp = tile + (row+ky)*TS_ + xbase;
            float v[10];
            #pragma unroll
            for (int q = 0; q < 10; q++) v[q] = rp[q];
            #pragma unroll
            for (int j = 0; j < 8; j++){
                #pragma unroll
                for (int kx = 0; kx < 3; kx++)
                    acc[j] += w[ky*3+kx] * v[j+kx];
            }
        }
    }

    float o[8];
    #pragma unroll
    for (int j = 0; j < 8; j++) o[j] = gelu_exact(accA[j]) * accB[j];

    float* gp = d_g + (((size_t)(b*NPATCH) + sy*32 + pat)*HF_ + c)*64 + row*8;
    *(float4*)(gp)     = make_float4(o[0],o[1],o[2],o[3]);
    *(float4*)(gp + 4) = make_float4(o[4],o[5],o[6],o[7]);
}

// ---------------------------------------------------------------------------
// Kernel 3: conv_out 1x1 GEMM, register-blocked 8o x 8px per thread.
// Thread px mapping: two contiguous 512B spans (4*lane and 128+4*lane) so
// each LDS.128 covers 32 distinct 16B chunks -> conflict-free.
// ---------------------------------------------------------------------------
__global__ void __launch_bounds__(256) k_out(float* __restrict__ out){
    __shared__ float gs[32*256];              // [c][4pat*64px]  32KB
    int t    = threadIdx.x;
    int b    = blockIdx.y;
    int pat0 = blockIdx.x * 4;
    int og   = t >> 5;                        // warp id: o = og*8..+7
    int pxg  = t & 31;
    int tpx0 = 4*pxg;                         // px 0..127 span
    int tpx1 = 128 + 4*pxg;                   // px 128..255 span

    ull acc[8][4];
    #pragma unroll
    for (int j = 0; j < 8; j++)
        #pragma unroll
        for (int k = 0; k < 4; k++) acc[j][k] = 0ull;

    const float* gb = d_g + ((size_t)(b*NPATCH) + pat0)*HF_*64;

    for (int cc = 0; cc < 4; cc++){
        __syncthreads();
        #pragma unroll
        for (int j = 0; j < 8; j++){
            int idx = t + j*256;              // 0..2047
            int pat = idx >> 9;               // 0..3
            int c   = (idx >> 4) & 31;
            int p4  = idx & 15;
            float4 v = __ldg((const float4*)(gb + ((size_t)pat*HF_ + cc*32 + c)*64 + p4*4));
            *(float4*)&gs[c*256 + pat*64 + p4*4] = v;
        }
        __syncthreads();
        const float* wp = &d_Wot[(cc*32)*64 + og*8];
        #pragma unroll 4
        for (int c = 0; c < 32; c++){
            float4 wa = __ldg((const float4*)(wp + c*64));
            float4 wb = __ldg((const float4*)(wp + c*64 + 4));
            ulonglong2 g0 = *(const ulonglong2*)&gs[c*256 + tpx0];
            ulonglong2 g1 = *(const ulonglong2*)&gs[c*256 + tpx1];
            float wv[8] = {wa.x,wa.y,wa.z,wa.w, wb.x,wb.y,wb.z,wb.w};
            #pragma unroll
            for (int j = 0; j < 8; j++){
                ull w2 = pack2(wv[j], wv[j]);
                ffma2(acc[j][0], w2, g0.x);
                ffma2(acc[j][1], w2, g0.y);
                ffma2(acc[j][2], w2, g1.x);
                ffma2(acc[j][3], w2, g1.y);
            }
        }
    }

    // store: tpx -> (local patch, row, col) -> global pixel
    int pl0 = tpx0 >> 6;  int r0 = (tpx0 >> 3) & 7;  int co0 = tpx0 & 7;
    int pl1 = tpx1 >> 6;  int r1 = (tpx1 >> 3) & 7;  int co1 = tpx1 & 7;
    int patg0 = pat0 + pl0, patg1 = pat0 + pl1;
    int off0 = (((patg0 >> 5) << 3) + r0)*HW_ + ((patg0 & 31) << 3) + co0;
    int off1 = (((patg1 >> 5) << 3) + r1)*HW_ + ((patg1 & 31) << 3) + co1;
    #pragma unroll
    for (int j = 0; j < 8; j++){
        int o = og*8 + j;
        float* ob = out + ((size_t)(b*DIM_) + o)*NPIX;
        float2 a0 = unpack2(acc[j][0]);
        float2 a1 = unpack2(acc[j][1]);
        float2 a2 = unpack2(acc[j][2]);
        float2 a3 = unpack2(acc[j][3]);
        *(float4*)(ob + off0) = make_float4(a0.x, a0.y, a1.x, a1.y);
        *(float4*)(ob + off1) = make_float4(a2.x, a2.y, a3.x, a3.y);
    }
}

// ---------------------------------------------------------------------------
extern "C" void kernel_launch(void* const* d_in, const int* in_sizes, int n_in,
                              void* d_out, int out_size){
    const float* x     = (const float*)d_in[0];
    const float* w_in  = (const float*)d_in[1];
    const float* w_dw  = (const float*)d_in[2];
    const float* filt  = (const float*)d_in[3];
    const float* w_out = (const float*)d_in[4];
    float* out = (float*)d_out;

    static int smem_set = 0;
    if (!smem_set){
        cudaFuncSetAttribute(k_main, cudaFuncAttributeMaxDynamicSharedMemorySize, SMEM_MAIN);
        smem_set = 1;
    }

    k_prep<<<64, 256>>>(filt, w_in, w_out);
    k_main<<<4096, 512, SMEM_MAIN>>>(x);
    k_dw<<<dim3(32, 128, 4), 256>>>(w_dw);
    k_out<<<dim3(256, 4), 256>>>(out);
}

// round 14
// speedup vs baseline: 1.0385x; 1.0385x over previous
#include <cuda_runtime.h>
#include <cstdint>

#define DIM_ 64
#define C2_  256
#define HF_  128
#define HW_  256
#define NPIX (HW_*HW_)
#define B_   4
#define NPATCH 1024   // 32x32 patches of 8x8

// scratch (device globals — allocation-free per harness rules)
__device__ float d_h[(size_t)B_*NPATCH*C2_*64];   // patch-major [b][pat][c2][64]
__device__ float d_g[(size_t)B_*NPATCH*HF_*64];   // patch-major [b][pat][c][64]
__device__ float d_Wt[DIM_*C2_];                  // w_in transposed [i][c]
__device__ float d_Wot[HF_*DIM_];                 // w_out transposed [c][o]

using ull = unsigned long long;
__device__ ull d_Kt2[64*C2_];                     // splat-packed kernels [uv][c]

__device__ __forceinline__ void ffma2(ull &d, ull a, ull b){
    asm("fma.rn.f32x2 %0, %1, %2, %0;" : "+l"(d) : "l"(a), "l"(b));
}
__device__ __forceinline__ ull pack2(float lo, float hi){
    ull r; asm("mov.b64 %0, {%1,%2};" : "=l"(r) : "f"(lo), "f"(hi)); return r;
}
__device__ __forceinline__ float2 unpack2(ull p){
    float2 r; asm("mov.b64 {%0,%1}, %2;" : "=f"(r.x), "=f"(r.y) : "l"(p)); return r;
}

// ---------------------------------------------------------------------------
// Kernel 0: spatial kernels K = irfft2(filt) (closed-form cosine sum),
// splat-packed [uv][c]; transpose w_in and w_out.
// ---------------------------------------------------------------------------
__global__ void k_prep(const float* __restrict__ filt, const float* __restrict__ win,
                       const float* __restrict__ wout){
    int t  = blockIdx.x*256 + threadIdx.x;   // 0..16383
    int c  = t & 255;
    int uv = t >> 8;                         // 0..63
    int u  = uv >> 3, v = uv & 7;
    float s = 0.f;
    #pragma unroll
    for (int ky = 0; ky < 8; ky++){
        #pragma unroll
        for (int kx = 0; kx < 5; kx++){
            float w = (kx==0 || kx==4) ? 1.f : 2.f;
            int m = (ky*u + kx*v) & 7;
            s += w * filt[c*40 + ky*5 + kx] * cospif(0.25f * (float)m);
        }
    }
    float sv = s * (1.f/64.f);
    d_Kt2[uv*256 + c] = pack2(sv, sv);
    d_Wt[uv*256 + c] = win[c*64 + uv];       // uv doubles as input-channel index
    if (t < HF_*DIM_){
        int cc = t >> 6, o = t & 63;
        d_Wot[cc*64 + o] = wout[o*128 + cc];
    }
}

__global__ void k_nop(){ }

// ---------------------------------------------------------------------------
// Kernel 1: fused conv_in (1x1) + per-patch circular conv (= FFT gating).
// 128-thread blocks, 2 blocks per (batch,patch) covering c2-halves.
// h2 register-resident; phase 2 in 8-pixel groups (32 acc regs).
// launch_bounds(128,3): 12 warps/SM at <=170 regs.
// ---------------------------------------------------------------------------
__global__ void __launch_bounds__(128, 3) k_main(const float* __restrict__ x){
    __shared__ ull xs2[64*32];    // 16KB [in_ch][pair] pair=(py',px)->(v[py'],v[py'+4])
    int blk   = blockIdx.x;
    int b     = blk >> 11;
    int pat   = (blk >> 1) & 1023;
    int halfc = blk & 1;
    int y0  = (pat >> 5) << 3;
    int x0  = (pat & 31) << 3;
    const float* xb = x + (size_t)b * DIM_ * NPIX;
    int t = threadIdx.x;

    // cooperative load of the 64ch x 8x8 input patch, interleaved into pairs
    for (int idx = t; idx < 512; idx += 128){
        int i = idx >> 3; int pyp = (idx >> 1) & 3; int hf = idx & 1;
        const float* p0 = xb + (size_t)i*NPIX + (y0+pyp)*HW_ + x0 + hf*4;
        float4 a  = *(const float4*)p0;
        float4 bb = *(const float4*)(p0 + 4*HW_);
        ull* dst = &xs2[i*32 + pyp*8 + hf*4];
        dst[0] = pack2(a.x, bb.x); dst[1] = pack2(a.y, bb.y);
        dst[2] = pack2(a.z, bb.z); dst[3] = pack2(a.w, bb.w);
    }
    __syncthreads();

    int c2 = halfc*128 + t;
    // phase 1: h[c2][p] = sum_i w_in[c2][i] * x[i][p]   (packed pairs)
    ull h2[32];
    #pragma unroll
    for (int k = 0; k < 32; k++) h2[k] = 0ull;
    #pragma unroll 4
    for (int i = 0; i < 64; i++){
        float wv = __ldg(&d_Wt[(i<<8) + c2]);
        ull wvv = pack2(wv, wv);
        const ulonglong2* xr = (const ulonglong2*)&xs2[i*32];
        #pragma unroll
        for (int q = 0; q < 16; q++){
            ulonglong2 xv = xr[q];
            ffma2(h2[2*q],   wvv, xv.x);
            ffma2(h2[2*q+1], wvv, xv.y);
        }
    }

    // phase 2: circular conv out[py][px] = sum_{u,v} K[u][v]*h[(py-u)&7][(px-v)&7]
    // dual-accumulator trick handles the pair swap across the mod-4 boundary.
    float* ob = d_h + (((size_t)(b*NPATCH) + pat)*C2_ + c2)*64;
    #pragma unroll
    for (int g = 0; g < 4; g++){
        ull accA[8], accB[8];
        #pragma unroll
        for (int j = 0; j < 8; j++){ accA[j]=0ull; accB[j]=0ull; }
        #pragma unroll
        for (int u = 0; u < 8; u++){
            int a = (g - u) & 7;
            const ull* hrow = &h2[(a & 3)*8];
            bool useA = (a < 4);
            #pragma unroll
            for (int v = 0; v < 8; v++){
                ull kvv = __ldg(&d_Kt2[((u<<3)+v)*256 + c2]);
                #pragma unroll
                for (int px = 0; px < 8; px++){
                    int col = (px - v) & 7;
                    if (useA) ffma2(accA[px], kvv, hrow[col]);
                    else      ffma2(accB[px], kvv, hrow[col]);
                }
            }
        }
        float lo[8], hi[8];
        #pragma unroll
        for (int px = 0; px < 8; px++){
            float2 A  = unpack2(accA[px]);
            float2 Bv = unpack2(accB[px]);
            lo[px] = A.x + Bv.y;     // out row g
            hi[px] = A.y + Bv.x;     // out row g+4
        }
        *(float4*)(ob + g*8)       = make_float4(lo[0],lo[1],lo[2],lo[3]);
        *(float4*)(ob + g*8 + 4)   = make_float4(lo[4],lo[5],lo[6],lo[7]);
        *(float4*)(ob + (g+4)*8)   = make_float4(hi[0],hi[1],hi[2],hi[3]);
        *(float4*)(ob + (g+4)*8+4) = make_float4(hi[4],hi[5],hi[6],hi[7]);
    }
}

// ---------------------------------------------------------------------------
// Kernel 2: depthwise 3x3 (SAME) + exact-gelu gate, patch-major in/out.
// smem tile row stride 265 (odd) -> conflict-free compute loads.
// ---------------------------------------------------------------------------
#define TS_ 265
__device__ __forceinline__ float gelu_exact(float v){
    return 0.5f * v * (1.f + erff(v * 0.70710678118654752f));
}

__global__ void __launch_bounds__(256) k_dw(const float* __restrict__ wdw){
    __shared__ float tA[10*TS_];
    __shared__ float tB[10*TS_];
    int t  = threadIdx.x;
    int sy = blockIdx.x;          // strip (patch row) 0..31
    int c  = blockIdx.y;          // 0..127
    int b  = blockIdx.z;
    int y0 = sy*8;

    if (t < 40){
        int r = t % 10;
        if (t < 10)      tA[r*TS_ + 0]   = 0.f;
        else if (t < 20) tA[r*TS_ + 257] = 0.f;
        else if (t < 30) tB[r*TS_ + 0]   = 0.f;
        else             tB[r*TS_ + 257] = 0.f;
    }

    #pragma unroll
    for (int half = 0; half < 2; half++){
        float* tile = half ? tB : tA;
        int ch = c + half*128;
        const float* src = d_h + ((size_t)(b*NPATCH))*C2_*64 + (size_t)ch*64;
        for (int f = t; f < 640; f += 256){
            int r  = f >> 6;          // 0..9
            int xq = f & 63;          // float4 index across 256 cols
            int y  = y0 - 1 + r;
            float4 v = make_float4(0,0,0,0);
            if (y >= 0 && y < 256){
                int pat = ((y>>3)<<5) + (xq>>1);
                int pix = ((y&7)<<3) + ((xq&1)<<2);
                v = __ldg((const float4*)(src + (size_t)pat*(C2_*64) + pix));
            }
            float* dst = tile + r*TS_ + 1 + xq*4;
            dst[0]=v.x; dst[1]=v.y; dst[2]=v.z; dst[3]=v.w;
        }
    }
    __syncthreads();

    int pat = t >> 3;                 // 0..31 (patch within strip)
    int row = t & 7;                  // 0..7
    int xbase = pat*8;

    float accA[8], accB[8];
    #pragma unroll
    for (int j = 0; j < 8; j++){ accA[j]=0.f; accB[j]=0.f; }

    #pragma unroll
    for (int half = 0; half < 2; half++){
        const float* tile = half ? tB : tA;
        const float* wp = wdw + (c + half*128)*9;
        float w[9];
        #pragma unroll
        for (int k = 0; k < 9; k++) w[k] = __ldg(wp + k);
        float* acc = half ? accB : accA;
        #pragma unroll
        for (int ky = 0; ky < 3; ky++){
            const float* rp = tile + (row+ky)*TS_ + xbase;
            float v[10];
            #pragma unroll
            for (int q = 0; q < 10; q++) v[q] = rp[q];
            #pragma unroll
            for (int j = 0; j < 8; j++){
                #pragma unroll
                for (int kx = 0; kx < 3; kx++)
                    acc[j] += w[ky*3+kx] * v[j+kx];
            }
        }
    }

    float o[8];
    #pragma unroll
    for (int j = 0; j < 8; j++) o[j] = gelu_exact(accA[j]) * accB[j];

    float* gp = d_g + (((size_t)(b*NPATCH) + sy*32 + pat)*HF_ + c)*64 + row*8;
    *(float4*)(gp)     = make_float4(o[0],o[1],o[2],o[3]);
    *(float4*)(gp + 4) = make_float4(o[4],o[5],o[6],o[7]);
}

// ---------------------------------------------------------------------------
// Kernel 3: conv_out 1x1 GEMM, register-blocked 8o x 8px per thread.
// Thread px mapping: two contiguous 512B spans -> conflict-free LDS.128.
// ---------------------------------------------------------------------------
__global__ void __launch_bounds__(256) k_out(float* __restrict__ out){
    __shared__ float gs[32*256];              // [c][4pat*64px]  32KB
    int t    = threadIdx.x;
    int b    = blockIdx.y;
    int pat0 = blockIdx.x * 4;
    int og   = t >> 5;                        // warp id: o = og*8..+7
    int pxg  = t & 31;
    int tpx0 = 4*pxg;                         // px 0..127 span
    int tpx1 = 128 + 4*pxg;                   // px 128..255 span

    ull acc[8][4];
    #pragma unroll
    for (int j = 0; j < 8; j++)
        #pragma unroll
        for (int k = 0; k < 4; k++) acc[j][k] = 0ull;

    const float* gb = d_g + ((size_t)(b*NPATCH) + pat0)*HF_*64;

    for (int cc = 0; cc < 4; cc++){
        __syncthreads();
        #pragma unroll
        for (int j = 0; j < 8; j++){
            int idx = t + j*256;              // 0..2047
            int pat = idx >> 9;               // 0..3
            int c   = (idx >> 4) & 31;
            int p4  = idx & 15;
            float4 v = __ldg((const float4*)(gb + ((size_t)pat*HF_ + cc*32 + c)*64 + p4*4));
            *(float4*)&gs[c*256 + pat*64 + p4*4] = v;
        }
        __syncthreads();
        const float* wp = &d_Wot[(cc*32)*64 + og*8];
        #pragma unroll 4
        for (int c = 0; c < 32; c++){
            float4 wa = __ldg((const float4*)(wp + c*64));
            float4 wb = __ldg((const float4*)(wp + c*64 + 4));
            ulonglong2 g0 = *(const ulonglong2*)&gs[c*256 + tpx0];
            ulonglong2 g1 = *(const ulonglong2*)&gs[c*256 + tpx1];
            float wv[8] = {wa.x,wa.y,wa.z,wa.w, wb.x,wb.y,wb.z,wb.w};
            #pragma unroll
            for (int j = 0; j < 8; j++){
                ull w2 = pack2(wv[j], wv[j]);
                ffma2(acc[j][0], w2, g0.x);
                ffma2(acc[j][1], w2, g0.y);
                ffma2(acc[j][2], w2, g1.x);
                ffma2(acc[j][3], w2, g1.y);
            }
        }
    }

    // store: tpx -> (local patch, row, col) -> global pixel
    int pl0 = tpx0 >> 6;  int r0 = (tpx0 >> 3) & 7;  int co0 = tpx0 & 7;
    int pl1 = tpx1 >> 6;  int r1 = (tpx1 >> 3) & 7;  int co1 = tpx1 & 7;
    int patg0 = pat0 + pl0, patg1 = pat0 + pl1;
    int off0 = (((patg0 >> 5) << 3) + r0)*HW_ + ((patg0 & 31) << 3) + co0;
    int off1 = (((patg1 >> 5) << 3) + r1)*HW_ + ((patg1 & 31) << 3) + co1;
    #pragma unroll
    for (int j = 0; j < 8; j++){
        int o = og*8 + j;
        float* ob = out + ((size_t)(b*DIM_) + o)*NPIX;
        float2 a0 = unpack2(acc[j][0]);
        float2 a1 = unpack2(acc[j][1]);
        float2 a2 = unpack2(acc[j][2]);
        float2 a3 = unpack2(acc[j][3]);
        *(float4*)(ob + off0) = make_float4(a0.x, a0.y, a1.x, a1.y);
        *(float4*)(ob + off1) = make_float4(a2.x, a2.y, a3.x, a3.y);
    }
}

// ---------------------------------------------------------------------------
extern "C" void kernel_launch(void* const* d_in, const int* in_sizes, int n_in,
                              void* d_out, int out_size){
    const float* x     = (const float*)d_in[0];
    const float* w_in  = (const float*)d_in[1];
    const float* w_dw  = (const float*)d_in[2];
    const float* filt  = (const float*)d_in[3];
    const float* w_out = (const float*)d_in[4];
    float* out = (float*)d_out;

    k_prep<<<64, 256>>>(filt, w_in, w_out);
    k_nop<<<1, 32>>>();
    k_nop<<<1, 32>>>();
    k_main<<<8192, 128>>>(x);
    k_dw<<<dim3(32, 128, 4), 256>>>(w_dw);
    k_out<<<dim3(256, 4), 256>>>(out);
}

// round 16
// speedup vs baseline: 1.1964x; 1.1521x over previous
#include <cuda_runtime.h>
#include <cstdint>

#define DIM_ 64
#define C2_  256
#define HF_  128
#define HW_  256
#define NPIX (HW_*HW_)
#define B_   4
#define NPATCH 1024   // 32x32 patches of 8x8

// scratch (device globals — allocation-free per harness rules)
__device__ float d_h[(size_t)B_*NPATCH*C2_*64];   // patch-major [b][pat][c2][64]
__device__ float d_g[(size_t)B_*NPATCH*HF_*64];   // patch-major [b][pat][c][64]
__device__ float d_Kt[64*C2_];                    // spatial kernels [uv][c]
__device__ float d_Wt[DIM_*C2_];                  // w_in transposed [i][c]
__device__ float d_Wot[HF_*DIM_];                 // w_out transposed [c][o]

using ull = unsigned long long;

__device__ __forceinline__ void ffma2(ull &d, ull a, ull b){
    asm("fma.rn.f32x2 %0, %1, %2, %0;" : "+l"(d) : "l"(a), "l"(b));
}
__device__ __forceinline__ ull pack2(float lo, float hi){
    ull r; asm("mov.b64 %0, {%1,%2};" : "=l"(r) : "f"(lo), "f"(hi)); return r;
}
__device__ __forceinline__ float2 unpack2(ull p){
    float2 r; asm("mov.b64 {%0,%1}, %2;" : "=f"(r.x), "=f"(r.y) : "l"(p)); return r;
}

// ---------------------------------------------------------------------------
// Kernel 0: spatial kernels K = irfft2(filt) (closed-form cosine sum),
// [uv][c]; transpose w_in and w_out.
// ---------------------------------------------------------------------------
__global__ void k_prep(const float* __restrict__ filt, const float* __restrict__ win,
                       const float* __restrict__ wout){
    int t  = blockIdx.x*256 + threadIdx.x;   // 0..16383
    int c  = t & 255;
    int uv = t >> 8;                         // 0..63
    int u  = uv >> 3, v = uv & 7;
    float s = 0.f;
    #pragma unroll
    for (int ky = 0; ky < 8; ky++){
        #pragma unroll
        for (int kx = 0; kx < 5; kx++){
            float w = (kx==0 || kx==4) ? 1.f : 2.f;
            int m = (ky*u + kx*v) & 7;
            s += w * filt[c*40 + ky*5 + kx] * cospif(0.25f * (float)m);
        }
    }
    d_Kt[uv*256 + c] = s * (1.f/64.f);
    d_Wt[uv*256 + c] = win[c*64 + uv];       // uv doubles as input-channel index
    if (t < HF_*DIM_){
        int cc = t >> 6, o = t & 63;
        d_Wot[cc*64 + o] = wout[o*128 + cc];
    }
}

__global__ void k_nop(){ }

// ---------------------------------------------------------------------------
// Kernel 1: fused conv_in (1x1) + per-patch circular conv (= FFT gating).
// One block per (batch, 8x8 patch); one thread per output channel c2.
// h2 register-resident; phase 2 in 8-pixel g-groups (32 acc regs).
// Measured-best config: 256 threads, no launch bounds (~234 regs, 1 CTA/SM).
// ---------------------------------------------------------------------------
__global__ void k_main(const float* __restrict__ x){
    __shared__ ull xs2[64*32];               // [in_ch][pair] pair=(py',px)->(h[py'],h[py'+4])
    int blk = blockIdx.x;
    int b   = blk >> 10;
    int pat = blk & 1023;
    int y0  = (pat >> 5) << 3;
    int x0  = (pat & 31) << 3;
    const float* xb = x + (size_t)b * DIM_ * NPIX;
    int t = threadIdx.x;

    for (int idx = t; idx < 512; idx += 256){
        int i = idx >> 3; int pyp = (idx >> 1) & 3; int hf = idx & 1;
        const float* p0 = xb + (size_t)i*NPIX + (y0+pyp)*HW_ + x0 + hf*4;
        float4 a  = *(const float4*)p0;
        float4 bb = *(const float4*)(p0 + 4*HW_);
        ull* dst = &xs2[i*32 + pyp*8 + hf*4];
        dst[0] = pack2(a.x, bb.x); dst[1] = pack2(a.y, bb.y);
        dst[2] = pack2(a.z, bb.z); dst[3] = pack2(a.w, bb.w);
    }
    __syncthreads();

    int c2 = t;
    ull h2[32];
    #pragma unroll
    for (int k = 0; k < 32; k++) h2[k] = 0ull;
    #pragma unroll 4
    for (int i = 0; i < 64; i++){
        float wv = __ldg(&d_Wt[(i<<8) + c2]);
        ull wvv = pack2(wv, wv);
        const ulonglong2* xr = (const ulonglong2*)&xs2[i*32];
        #pragma unroll
        for (int q = 0; q < 16; q++){
            ulonglong2 xv = xr[q];
            ffma2(h2[2*q],   wvv, xv.x);
            ffma2(h2[2*q+1], wvv, xv.y);
        }
    }

    float* ob = d_h + (((size_t)(b*NPATCH) + pat)*C2_ + c2)*64;
    #pragma unroll
    for (int g = 0; g < 4; g++){
        ull accA[8], accB[8];
        #pragma unroll
        for (int j = 0; j < 8; j++){ accA[j]=0ull; accB[j]=0ull; }
        #pragma unroll
        for (int u = 0; u < 8; u++){
            int a = (g - u) & 7;
            const ull* hrow = &h2[(a & 3)*8];
            bool useA = (a < 4);
            #pragma unroll
            for (int v = 0; v < 8; v++){
                float kv = __ldg(&d_Kt[((u<<3)+v)*256 + c2]);
                ull kvv = pack2(kv, kv);
                #pragma unroll
                for (int px = 0; px < 8; px++){
                    int col = (px - v) & 7;
                    if (useA) ffma2(accA[px], kvv, hrow[col]);
                    else      ffma2(accB[px], kvv, hrow[col]);
                }
            }
        }
        float lo[8], hi[8];
        #pragma unroll
        for (int px = 0; px < 8; px++){
            float2 A  = unpack2(accA[px]);
            float2 Bv = unpack2(accB[px]);
            lo[px] = A.x + Bv.y;     // out row g
            hi[px] = A.y + Bv.x;     // out row g+4
        }
        *(float4*)(ob + g*8)       = make_float4(lo[0],lo[1],lo[2],lo[3]);
        *(float4*)(ob + g*8 + 4)   = make_float4(lo[4],lo[5],lo[6],lo[7]);
        *(float4*)(ob + (g+4)*8)   = make_float4(hi[0],hi[1],hi[2],hi[3]);
        *(float4*)(ob + (g+4)*8+4) = make_float4(hi[4],hi[5],hi[6],hi[7]);
    }
}

// ---------------------------------------------------------------------------
// Kernel 2: depthwise 3x3 (SAME) + exact-gelu gate, patch-major in/out.
// smem tile row stride 265 (odd) -> conflict-free compute loads.
// ---------------------------------------------------------------------------
#define TS_ 265
__device__ __forceinline__ float gelu_exact(float v){
    return 0.5f * v * (1.f + erff(v * 0.70710678118654752f));
}

__global__ void __launch_bounds__(256) k_dw(const float* __restrict__ wdw){
    __shared__ float tA[10*TS_];
    __shared__ float tB[10*TS_];
    int t  = threadIdx.x;
    int sy = blockIdx.x;          // strip (patch row) 0..31
    int c  = blockIdx.y;          // 0..127
    int b  = blockIdx.z;
    int y0 = sy*8;

    if (t < 40){
        int r = t % 10;
        if (t < 10)      tA[r*TS_ + 0]   = 0.f;
        else if (t < 20) tA[r*TS_ + 257] = 0.f;
        else if (t < 30) tB[r*TS_ + 0]   = 0.f;
        else             tB[r*TS_ + 257] = 0.f;
    }

    #pragma unroll
    for (int half = 0; half < 2; half++){
        float* tile = half ? tB : tA;
        int ch = c + half*128;
        const float* src = d_h + ((size_t)(b*NPATCH))*C2_*64 + (size_t)ch*64;
        for (int f = t; f < 640; f += 256){
            int r  = f >> 6;          // 0..9
            int xq = f & 63;          // float4 index across 256 cols
            int y  = y0 - 1 + r;
            float4 v = make_float4(0,0,0,0);
            if (y >= 0 && y < 256){
                int pat = ((y>>3)<<5) + (xq>>1);
                int pix = ((y&7)<<3) + ((xq&1)<<2);
                v = __ldg((const float4*)(src + (size_t)pat*(C2_*64) + pix));
            }
            float* dst = tile + r*TS_ + 1 + xq*4;
            dst[0]=v.x; dst[1]=v.y; dst[2]=v.z; dst[3]=v.w;
        }
    }
    __syncthreads();

    int pat = t >> 3;                 // 0..31 (patch within strip)
    int row = t & 7;                  // 0..7
    int xbase = pat*8;

    float accA[8], accB[8];
    #pragma unroll
    for (int j = 0; j < 8; j++){ accA[j]=0.f; accB[j]=0.f; }

    #pragma unroll
    for (int half = 0; half < 2; half++){
        const float* tile = half ? tB : tA;
        const float* wp = wdw + (c + half*128)*9;
        float w[9];
        #pragma unroll
        for (int k = 0; k < 9; k++) w[k] = __ldg(wp + k);
        float* acc = half ? accB : accA;
        #pragma unroll
        for (int ky = 0; ky < 3; ky++){
            const float* rp = tile + (row+ky)*TS_ + xbase;
            float v[10];
            #pragma unroll
            for (int q = 0; q < 10; q++) v[q] = rp[q];
            #pragma unroll
            for (int j = 0; j < 8; j++){
                #pragma unroll
                for (int kx = 0; kx < 3; kx++)
                    acc[j] += w[ky*3+kx] * v[j+kx];
            }
        }
    }

    float o[8];
    #pragma unroll
    for (int j = 0; j < 8; j++) o[j] = gelu_exact(accA[j]) * accB[j];

    float* gp = d_g + (((size_t)(b*NPATCH) + sy*32 + pat)*HF_ + c)*64 + row*8;
    *(float4*)(gp)     = make_float4(o[0],o[1],o[2],o[3]);
    *(float4*)(gp + 4) = make_float4(o[4],o[5],o[6],o[7]);
}

// ---------------------------------------------------------------------------
// Kernel 3: conv_out 1x1 GEMM, register-blocked 8o x 8px per thread.
// Thread px mapping: two contiguous 512B spans -> conflict-free LDS.128.
// ---------------------------------------------------------------------------
__global__ void __launch_bounds__(256) k_out(float* __restrict__ out){
    __shared__ float gs[32*256];              // [c][4pat*64px]  32KB
    int t    = threadIdx.x;
    int b    = blockIdx.y;
    int pat0 = blockIdx.x * 4;
    int og   = t >> 5;                        // warp id: o = og*8..+7
    int pxg  = t & 31;
    int tpx0 = 4*pxg;                         // px 0..127 span
    int tpx1 = 128 + 4*pxg;                   // px 128..255 span

    ull acc[8][4];
    #pragma unroll
    for (int j = 0; j < 8; j++)
        #pragma unroll
        for (int k = 0; k < 4; k++) acc[j][k] = 0ull;

    const float* gb = d_g + ((size_t)(b*NPATCH) + pat0)*HF_*64;

    for (int cc = 0; cc < 4; cc++){
        __syncthreads();
        #pragma unroll
        for (int j = 0; j < 8; j++){
            int idx = t + j*256;              // 0..2047
            int pat = idx >> 9;               // 0..3
            int c   = (idx >> 4) & 31;
            int p4  = idx & 15;
            float4 v = __ldg((const float4*)(gb + ((size_t)pat*HF_ + cc*32 + c)*64 + p4*4));
            *(float4*)&gs[c*256 + pat*64 + p4*4] = v;
        }
        __syncthreads();
        const float* wp = &d_Wot[(cc*32)*64 + og*8];
        #pragma unroll 4
        for (int c = 0; c < 32; c++){
            float4 wa = __ldg((const float4*)(wp + c*64));
            float4 wb = __ldg((const float4*)(wp + c*64 + 4));
            ulonglong2 g0 = *(const ulonglong2*)&gs[c*256 + tpx0];
            ulonglong2 g1 = *(const ulonglong2*)&gs[c*256 + tpx1];
            float wv[8] = {wa.x,wa.y,wa.z,wa.w, wb.x,wb.y,wb.z,wb.w};
            #pragma unroll
            for (int j = 0; j < 8; j++){
                ull w2 = pack2(wv[j], wv[j]);
                ffma2(acc[j][0], w2, g0.x);
                ffma2(acc[j][1], w2, g0.y);
                ffma2(acc[j][2], w2, g1.x);
                ffma2(acc[j][3], w2, g1.y);
            }
        }
    }

    // store: tpx -> (local patch, row, col) -> global pixel
    int pl0 = tpx0 >> 6;  int r0 = (tpx0 >> 3) & 7;  int co0 = tpx0 & 7;
    int pl1 = tpx1 >> 6;  int r1 = (tpx1 >> 3) & 7;  int co1 = tpx1 & 7;
    int patg0 = pat0 + pl0, patg1 = pat0 + pl1;
    int off0 = (((patg0 >> 5) << 3) + r0)*HW_ + ((patg0 & 31) << 3) + co0;
    int off1 = (((patg1 >> 5) << 3) + r1)*HW_ + ((patg1 & 31) << 3) + co1;
    #pragma unroll
    for (int j = 0; j < 8; j++){
        int o = og*8 + j;
        float* ob = out + ((size_t)(b*DIM_) + o)*NPIX;
        float2 a0 = unpack2(acc[j][0]);
        float2 a1 = unpack2(acc[j][1]);
        float2 a2 = unpack2(acc[j][2]);
        float2 a3 = unpack2(acc[j][3]);
        *(float4*)(ob + off0) = make_float4(a0.x, a0.y, a1.x, a1.y);
        *(float4*)(ob + off1) = make_float4(a2.x, a2.y, a3.x, a3.y);
    }
}

// ---------------------------------------------------------------------------
extern "C" void kernel_launch(void* const* d_in, const int* in_sizes, int n_in,
                              void* d_out, int out_size){
    const float* x     = (const float*)d_in[0];
    const float* w_in  = (const float*)d_in[1];
    const float* w_dw  = (const float*)d_in[2];
    const float* filt  = (const float*)d_in[3];
    const float* w_out = (const float*)d_in[4];
    float* out = (float*)d_out;

    k_prep<<<64, 256>>>(filt, w_in, w_out);
    k_nop<<<1, 32>>>();
    k_nop<<<1, 32>>>();
    k_main<<<4096, 256>>>(x);
    k_dw<<<dim3(32, 128, 4), 256>>>(w_dw);
    k_out<<<dim3(256, 4), 256>>>(out);
}